// round 6
// baseline (speedup 1.0000x reference)
#include <cuda_runtime.h>
#include <cuda_bf16.h>

#define N_NODES 100000
#define N_EDGES 1600000
#define NRELS 8
#define HID 128
#define N_TYPES 250
#define NG 64
#define NCLS 49
#define MAXDEG 64
#define MASK_SENTINEL (-(1 << 29))

// ---- scratch (device globals; no allocation allowed) ----
__device__ __align__(16) float g_projr[N_TYPES * HID];                 // fp32 root proj, 128 KB
__device__ __align__(16) __nv_bfloat16 g_projh[N_TYPES * NRELS * HID]; // bf16 rel proj, 512 KB
__device__ int g_cur[N_NODES];                                         // slot counter / mask sentinel
__device__ unsigned short g_csr[(size_t)N_NODES * MAXDEG];             // 12.8 MB keys (t*8+r)
__device__ unsigned char g_type8[N_NODES];                             // 100 KB, L1-resident
__device__ int g_list[N_NODES];                                        // packed n|g<<17|t<<23
__device__ int g_ncount = 0;
__device__ float g_seg[NG * HID];
__device__ float g_segcnt[NG];

// proj = emb @ [w_rel_0..7 | w_root]; rel part stored bf16, root part fp32.
// Also resets g_ncount for the following k_prep (stream-ordered).
__global__ void k_proj(const float* __restrict__ emb,
                       const float* __restrict__ w_rel,
                       const float* __restrict__ w_root) {
    __shared__ float semb[10][128];
    int bx = blockIdx.x;           // 0..7 = rel r, 8 = root
    int y0 = blockIdx.y * 10;
    int tid = threadIdx.x;
    if (bx == 8 && blockIdx.y == 0 && tid == 0) g_ncount = 0;
    for (int idx = tid; idx < 10 * 128; idx += 128) {
        int row = idx >> 7, d = idx & 127;
        semb[row][d] = emb[(y0 + row) * 128 + d];
    }
    __syncthreads();
    float acc[10];
#pragma unroll
    for (int t = 0; t < 10; t++) acc[t] = 0.f;
    const float* wp = (bx < 8) ? (w_rel + (size_t)bx * 128 * 128 + tid)
                               : (w_root + tid);
#pragma unroll 4
    for (int d = 0; d < 128; d++) {
        float wv = wp[(size_t)d * 128];
#pragma unroll
        for (int t = 0; t < 10; t++) acc[t] += semb[t][d] * wv;
    }
    if (bx < 8) {
#pragma unroll
        for (int t = 0; t < 10; t++)
            g_projh[(y0 + t) * (NRELS * HID) + bx * HID + tid] = __float2bfloat16_rn(acc[t]);
    } else {
#pragma unroll
        for (int t = 0; t < 10; t++)
            g_projr[(y0 + t) * HID + tid] = acc[t];
    }
}

// One coalesced pass over nodes: type byte-table, g_cur mask-sentinel init,
// warp-aggregated compaction, match-aggregated per-graph counts, seg zeroing.
__global__ void k_prep(const int* __restrict__ x,
                       const int* __restrict__ nt,
                       const int* __restrict__ batch) {
    int n = blockIdx.x * blockDim.x + threadIdx.x;
    int lane = threadIdx.x & 31;
    if (n < NG * HID) g_seg[n] = 0.f;
    if (n < NG) g_segcnt[n] = 0.f;
    bool valid = (n < N_NODES);
    int t = 0, m = 1, g = 0;
    if (valid) {
        t = x[n]; m = nt[n]; g = batch[n];
        g_type8[n] = (unsigned char)t;
        g_cur[n] = (m == 0) ? 0 : MASK_SENTINEL;
    }
    bool keep = valid && (m == 0);
    unsigned full = 0xffffffffu;
    unsigned ball = __ballot_sync(full, keep);
    int cnt = __popc(ball);
    int base = 0;
    if (lane == 0 && cnt) base = atomicAdd(&g_ncount, cnt);
    base = __shfl_sync(full, base, 0);
    if (keep) {
        int pos = base + __popc(ball & ((1u << lane) - 1u));
        g_list[pos] = n | (g << 17) | (t << 23);
    }
    unsigned grp = __match_any_sync(full, keep ? g : -1);
    if (keep && lane == (__ffs(grp) - 1))
        atomicAdd(&g_segcnt[g], (float)__popc(grp));
}

// Bucket-CSR build: 8 edges/thread, unconditional atomics (mask folded into
// g_cur sentinel -> negative slot), hoisted independent type loads.
__global__ void __launch_bounds__(256, 8) k_build(const int* __restrict__ ei,
                                                  const int* __restrict__ et) {
    int e8 = blockIdx.x * blockDim.x + threadIdx.x;
    if (e8 >= N_EDGES / 8) return;
    const int4* s4 = (const int4*)ei;
    const int4* d4 = (const int4*)(ei + N_EDGES);
    const int4* r4 = (const int4*)et;
    int4 sa = s4[e8 * 2], sb = s4[e8 * 2 + 1];
    int4 da = d4[e8 * 2], db = d4[e8 * 2 + 1];
    int4 ra = r4[e8 * 2], rb = r4[e8 * 2 + 1];
    int ss[8] = {sa.x, sa.y, sa.z, sa.w, sb.x, sb.y, sb.z, sb.w};
    int dd[8] = {da.x, da.y, da.z, da.w, db.x, db.y, db.z, db.w};
    int rr[8] = {ra.x, ra.y, ra.z, ra.w, rb.x, rb.y, rb.z, rb.w};
    int tt[8];
#pragma unroll
    for (int j = 0; j < 8; j++) tt[j] = g_type8[ss[j]];
    int slot[8];
#pragma unroll
    for (int j = 0; j < 8; j++) slot[j] = atomicAdd(&g_cur[dd[j]], 1);
#pragma unroll
    for (int j = 0; j < 8; j++) {
        if ((unsigned)slot[j] < MAXDEG)
            g_csr[(size_t)dd[j] * MAXDEG + slot[j]] = (unsigned short)(tt[j] * NRELS + rr[j]);
    }
}

// One warp per unmasked node. Rel counts via ballots, (key,weight) staged in
// smem once, then unroll-x8 broadcast-LDS + LDG.64 message loop, ReLU, red.v4.
__global__ void k_gather(const float* __restrict__ bias) {
    __shared__ float2 sbuf[8][MAXDEG];
    int gt = blockIdx.x * blockDim.x + threadIdx.x;
    int idx = gt >> 5;
    int lane = gt & 31;
    int wslot = (threadIdx.x >> 5);
    if (idx >= g_ncount) return;
    int packed = g_list[idx];
    int n = packed & 0x1ffff;
    int g = (packed >> 17) & 63;
    int t0 = packed >> 23;

    float4 acc = ((const float4*)g_projr)[t0 * 32 + lane];
    float4 b = ((const float4*)bias)[lane];
    acc.x += b.x; acc.y += b.y; acc.z += b.z; acc.w += b.w;

    int deg = min(g_cur[n], MAXDEG);
    const unsigned short* row = g_csr + (size_t)n * MAXDEG;
    int ka = row[lane];
    int kb = row[lane + 32];
    int ra = ka & 7, rb = kb & 7;

    unsigned mA = (deg >= 32) ? 0xffffffffu : ((1u << deg) - 1u);
    int d2 = deg - 32;
    unsigned mB = (d2 <= 0) ? 0u : ((d2 >= 32) ? 0xffffffffu : ((1u << d2) - 1u));
    unsigned full = 0xffffffffu;
    unsigned a0 = __ballot_sync(full, ra & 1), a1 = __ballot_sync(full, ra & 2), a2 = __ballot_sync(full, ra & 4);
    unsigned b0 = __ballot_sync(full, rb & 1), b1 = __ballot_sync(full, rb & 2), b2 = __ballot_sync(full, rb & 4);
    unsigned sa = ((ra & 1) ? a0 : ~a0) & ((ra & 2) ? a1 : ~a1) & ((ra & 4) ? a2 : ~a2);
    unsigned sb = ((ra & 1) ? b0 : ~b0) & ((ra & 2) ? b1 : ~b1) & ((ra & 4) ? b2 : ~b2);
    int ca = __popc(sa & mA) + __popc(sb & mB);
    float wa = 1.0f / fmaxf((float)ca, 1.0f);
    unsigned ua = ((rb & 1) ? a0 : ~a0) & ((rb & 2) ? a1 : ~a1) & ((rb & 4) ? a2 : ~a2);
    unsigned ub = ((rb & 1) ? b0 : ~b0) & ((rb & 2) ? b1 : ~b1) & ((rb & 4) ? b2 : ~b2);
    int cb = __popc(ua & mA) + __popc(ub & mB);
    float wb = 1.0f / fmaxf((float)cb, 1.0f);

    sbuf[wslot][lane]      = make_float2(wa, __int_as_float(ka));
    sbuf[wslot][lane + 32] = make_float2(wb, __int_as_float(kb));
    __syncwarp();

    const uint2* ph = (const uint2*)g_projh;
    int degR = (deg + 7) & ~7;
    for (int i = 0; i < degR; i += 8) {
#pragma unroll
        for (int j = 0; j < 8; j++) {
            int i2 = i + j;
            float2 kw = sbuf[wslot][i2];
            float w = (i2 < deg) ? kw.x : 0.f;
            int key = __float_as_int(kw.y);
            uint2 v = ph[(size_t)key * 32 + lane];
            float e0 = __uint_as_float(v.x << 16);
            float e1 = __uint_as_float(v.x & 0xffff0000u);
            float e2 = __uint_as_float(v.y << 16);
            float e3 = __uint_as_float(v.y & 0xffff0000u);
            acc.x += e0 * w; acc.y += e1 * w; acc.z += e2 * w; acc.w += e3 * w;
        }
    }

    acc.x = fmaxf(acc.x, 0.f); acc.y = fmaxf(acc.y, 0.f);
    acc.z = fmaxf(acc.z, 0.f); acc.w = fmaxf(acc.w, 0.f);

    float* dstp = &g_seg[g * HID + lane * 4];
    asm volatile("red.global.add.v4.f32 [%0], {%1,%2,%3,%4};"
                 :: "l"(dstp), "f"(acc.x), "f"(acc.y), "f"(acc.z), "f"(acc.w)
                 : "memory");
}

// out[g][o] = (seg[g]/max(cnt,1)) . lin_w[o] + lin_b[o]
__global__ void k_out(const float* __restrict__ lw,
                      const float* __restrict__ lb,
                      float* __restrict__ out) {
    __shared__ float s[128];
    int g = blockIdx.x, tid = threadIdx.x;
    float c = g_segcnt[g];
    float inv = 1.0f / fmaxf(c, 1.0f);
    s[tid] = g_seg[g * HID + tid] * inv;
    __syncthreads();
    if (tid < NCLS) {
        float acc = lb[tid];
#pragma unroll 4
        for (int d = 0; d < 128; d++) acc += s[d] * lw[tid * 128 + d];
        out[g * NCLS + tid] = acc;
    }
}

extern "C" void kernel_launch(void* const* d_in, const int* in_sizes, int n_in,
                              void* d_out, int out_size) {
    int o = (n_in >= 12) ? 1 : 0;
    const int* x     = (const int*)d_in[0];
    const int* ei    = (const int*)d_in[1];
    const int* et    = (const int*)d_in[2];
    const int* batch = (const int*)d_in[3];
    const int* nt    = (const int*)d_in[4];
    const float* emb    = (const float*)d_in[5 + o];
    const float* w_root = (const float*)d_in[6 + o];
    const float* w_rel  = (const float*)d_in[7 + o];
    const float* bias   = (const float*)d_in[8 + o];
    const float* lw     = (const float*)d_in[9 + o];
    const float* lb     = (const float*)d_in[10 + o];
    float* out = (float*)d_out;

    k_proj<<<dim3(9, 25), 128>>>(emb, w_rel, w_root);
    k_prep<<<(N_NODES + 255) / 256, 256>>>(x, nt, batch);
    k_build<<<(N_EDGES / 8 + 255) / 256, 256>>>(ei, et);
    k_gather<<<(N_NODES * 32 + 255) / 256, 256>>>(bias);
    k_out<<<NG, 128>>>(lw, lb, out);
    (void)in_sizes; (void)out_size;
}

// round 7
// speedup vs baseline: 1.0004x; 1.0004x over previous
#include <cuda_runtime.h>
#include <cuda_bf16.h>

#define N_NODES 100000
#define N_EDGES 1600000
#define NRELS 8
#define HID 128
#define N_TYPES 250
#define NG 64
#define NCLS 49
#define MAXDEG 64

// ---- scratch (device globals; no allocation allowed) ----
__device__ __align__(16) float g_projr[N_TYPES * HID];                // fp32 root proj, 128 KB
__device__ __align__(16) float g_projf[N_TYPES * NRELS * HID];        // fp32 rel proj, 1 MB (L2-resident)
__device__ int g_cur[N_NODES];                                        // bucket fill
__device__ unsigned short g_csr[(size_t)N_NODES * MAXDEG];            // 12.8 MB keys (t*8+r)
__device__ unsigned char g_type8[N_NODES];                            // 100 KB
__device__ unsigned char g_msk[N_NODES];                              // 100 KB
__device__ int g_list[N_NODES];                                       // packed n|g<<17|t<<23
__device__ int g_ncount = 0;
__device__ float g_seg[NG * HID];
__device__ float g_segcnt[NG];

// proj = emb @ [w_rel_0..7 | w_root], all fp32. Also resets g_ncount.
__global__ void k_proj(const float* __restrict__ emb,
                       const float* __restrict__ w_rel,
                       const float* __restrict__ w_root) {
    __shared__ float semb[10][128];
    int bx = blockIdx.x;           // 0..7 = rel r, 8 = root
    int y0 = blockIdx.y * 10;
    int tid = threadIdx.x;
    if (bx == 8 && blockIdx.y == 0 && tid == 0) g_ncount = 0;
    for (int idx = tid; idx < 10 * 128; idx += 128) {
        int row = idx >> 7, d = idx & 127;
        semb[row][d] = emb[(y0 + row) * 128 + d];
    }
    __syncthreads();
    float acc[10];
#pragma unroll
    for (int t = 0; t < 10; t++) acc[t] = 0.f;
    const float* wp = (bx < 8) ? (w_rel + (size_t)bx * 128 * 128 + tid)
                               : (w_root + tid);
#pragma unroll 4
    for (int d = 0; d < 128; d++) {
        float wv = wp[(size_t)d * 128];
#pragma unroll
        for (int t = 0; t < 10; t++) acc[t] += semb[t][d] * wv;
    }
    if (bx < 8) {
#pragma unroll
        for (int t = 0; t < 10; t++)
            g_projf[((y0 + t) * NRELS + bx) * HID + tid] = acc[t];
    } else {
#pragma unroll
        for (int t = 0; t < 10; t++)
            g_projr[(y0 + t) * HID + tid] = acc[t];
    }
}

// One coalesced pass over nodes: byte tables, counter reset, warp-aggregated
// compaction, match-aggregated per-graph counts, seg zeroing.
__global__ void k_prep(const int* __restrict__ x,
                       const int* __restrict__ nt,
                       const int* __restrict__ batch) {
    int n = blockIdx.x * blockDim.x + threadIdx.x;
    int lane = threadIdx.x & 31;
    if (n < NG * HID) g_seg[n] = 0.f;
    if (n < NG) g_segcnt[n] = 0.f;
    bool valid = (n < N_NODES);
    int t = 0, m = 1, g = 0;
    if (valid) {
        t = x[n]; m = nt[n]; g = batch[n];
        g_type8[n] = (unsigned char)t;
        g_msk[n] = (m == 0) ? 1 : 0;
        g_cur[n] = 0;
    }
    bool keep = valid && (m == 0);
    unsigned full = 0xffffffffu;
    unsigned ball = __ballot_sync(full, keep);
    int cnt = __popc(ball);
    int base = 0;
    if (lane == 0 && cnt) base = atomicAdd(&g_ncount, cnt);
    base = __shfl_sync(full, base, 0);
    if (keep) {
        int pos = base + __popc(ball & ((1u << lane) - 1u));
        g_list[pos] = n | (g << 17) | (t << 23);
    }
    unsigned grp = __match_any_sync(full, keep ? g : -1);
    if (keep && lane == (__ffs(grp) - 1))
        atomicAdd(&g_segcnt[g], (float)__popc(grp));
}

// Bucket-CSR build: 4 edges/thread (full occupancy), hoisted mask/type loads,
// conditional atomic (no masked-destination atomics).
__global__ void __launch_bounds__(256, 8) k_build(const int* __restrict__ ei,
                                                  const int* __restrict__ et) {
    int e4 = blockIdx.x * blockDim.x + threadIdx.x;
    if (e4 >= N_EDGES / 4) return;
    int4 sv = ((const int4*)ei)[e4];
    int4 dv = ((const int4*)(ei + N_EDGES))[e4];
    int4 rv = ((const int4*)et)[e4];
    int ss[4] = {sv.x, sv.y, sv.z, sv.w};
    int dd[4] = {dv.x, dv.y, dv.z, dv.w};
    int rr[4] = {rv.x, rv.y, rv.z, rv.w};
    unsigned char mk[4];
    int tt[4];
#pragma unroll
    for (int j = 0; j < 4; j++) mk[j] = g_msk[dd[j]];
#pragma unroll
    for (int j = 0; j < 4; j++) tt[j] = g_type8[ss[j]];
#pragma unroll
    for (int j = 0; j < 4; j++) {
        if (!mk[j]) continue;
        int slot = atomicAdd(&g_cur[dd[j]], 1);
        if (slot < MAXDEG)
            g_csr[(size_t)dd[j] * MAXDEG + slot] = (unsigned short)(tt[j] * NRELS + rr[j]);
    }
}

// One warp per unmasked node. Rel counts via ballots; smem stage holds
// fully-resolved ({w,w} packed, byte-offset) per message; inner loop is
// LDS.128 + LDG.128 + 2x fma.rn.f32x2, unrolled x8.
__global__ void k_gather(const float* __restrict__ bias) {
    __shared__ ulonglong2 sbuf[8][MAXDEG];
    int gt = blockIdx.x * blockDim.x + threadIdx.x;
    int idx = gt >> 5;
    int lane = gt & 31;
    int wslot = threadIdx.x >> 5;
    if (idx >= g_ncount) return;
    int packed = g_list[idx];
    int n = packed & 0x1ffff;
    int g = (packed >> 17) & 63;
    int t0 = packed >> 23;

    float4 rt = ((const float4*)g_projr)[t0 * 32 + lane];
    float4 bb = ((const float4*)bias)[lane];
    float e0 = rt.x + bb.x, e1 = rt.y + bb.y, e2 = rt.z + bb.z, e3 = rt.w + bb.w;
    unsigned long long acc01, acc23;
    asm("mov.b64 %0, {%1,%2};" : "=l"(acc01) : "f"(e0), "f"(e1));
    asm("mov.b64 %0, {%1,%2};" : "=l"(acc23) : "f"(e2), "f"(e3));

    int deg = min(g_cur[n], MAXDEG);
    const unsigned short* row = g_csr + (size_t)n * MAXDEG;
    int ka = row[lane];
    int kb = row[lane + 32];
    int ra = ka & 7, rb = kb & 7;

    unsigned mA = (deg >= 32) ? 0xffffffffu : ((1u << deg) - 1u);
    int d2 = deg - 32;
    unsigned mB = (d2 <= 0) ? 0u : ((d2 >= 32) ? 0xffffffffu : ((1u << d2) - 1u));
    unsigned full = 0xffffffffu;
    unsigned a0 = __ballot_sync(full, ra & 1), a1 = __ballot_sync(full, ra & 2), a2 = __ballot_sync(full, ra & 4);
    unsigned b0 = __ballot_sync(full, rb & 1), b1 = __ballot_sync(full, rb & 2), b2 = __ballot_sync(full, rb & 4);
    unsigned sa = ((ra & 1) ? a0 : ~a0) & ((ra & 2) ? a1 : ~a1) & ((ra & 4) ? a2 : ~a2);
    unsigned sb = ((ra & 1) ? b0 : ~b0) & ((ra & 2) ? b1 : ~b1) & ((ra & 4) ? b2 : ~b2);
    int ca = __popc(sa & mA) + __popc(sb & mB);
    float wa = 1.0f / fmaxf((float)ca, 1.0f);
    unsigned ua = ((rb & 1) ? a0 : ~a0) & ((rb & 2) ? a1 : ~a1) & ((rb & 4) ? a2 : ~a2);
    unsigned ub = ((rb & 1) ? b0 : ~b0) & ((rb & 2) ? b1 : ~b1) & ((rb & 4) ? b2 : ~b2);
    int cb = __popc(ua & mA) + __popc(ub & mB);
    float wb = 1.0f / fmaxf((float)cb, 1.0f);

    // Stage resolved messages: pads get w=0 (stale CSR keys are always in-range).
    unsigned wab = __float_as_uint((lane < deg) ? wa : 0.f);
    unsigned wbb = __float_as_uint((lane + 32 < deg) ? wb : 0.f);
    sbuf[wslot][lane] = make_ulonglong2(((unsigned long long)wab << 32) | wab,
                                        (unsigned long long)(ka * 512));
    sbuf[wslot][lane + 32] = make_ulonglong2(((unsigned long long)wbb << 32) | wbb,
                                             (unsigned long long)(kb * 512));
    __syncwarp();

    const char* basep = (const char*)g_projf + lane * 16;
    int degR = (deg + 7) & ~7;
    for (int i = 0; i < degR; i += 8) {
#pragma unroll
        for (int j = 0; j < 8; j++) {
            ulonglong2 s = sbuf[wslot][i + j];
            const char* p = basep + s.y;
            unsigned long long v01, v23;
            asm("ld.global.nc.v2.u64 {%0,%1}, [%2];" : "=l"(v01), "=l"(v23) : "l"(p));
            asm("fma.rn.f32x2 %0, %1, %2, %0;" : "+l"(acc01) : "l"(v01), "l"(s.x));
            asm("fma.rn.f32x2 %0, %1, %2, %0;" : "+l"(acc23) : "l"(v23), "l"(s.x));
        }
    }

    float r0, r1, r2, r3;
    asm("mov.b64 {%0,%1}, %2;" : "=f"(r0), "=f"(r1) : "l"(acc01));
    asm("mov.b64 {%0,%1}, %2;" : "=f"(r2), "=f"(r3) : "l"(acc23));
    r0 = fmaxf(r0, 0.f); r1 = fmaxf(r1, 0.f);
    r2 = fmaxf(r2, 0.f); r3 = fmaxf(r3, 0.f);

    float* dstp = &g_seg[g * HID + lane * 4];
    asm volatile("red.global.add.v4.f32 [%0], {%1,%2,%3,%4};"
                 :: "l"(dstp), "f"(r0), "f"(r1), "f"(r2), "f"(r3)
                 : "memory");
}

// out[g][o] = (seg[g]/max(cnt,1)) . lin_w[o] + lin_b[o]
__global__ void k_out(const float* __restrict__ lw,
                      const float* __restrict__ lb,
                      float* __restrict__ out) {
    __shared__ float s[128];
    int g = blockIdx.x, tid = threadIdx.x;
    float c = g_segcnt[g];
    float inv = 1.0f / fmaxf(c, 1.0f);
    s[tid] = g_seg[g * HID + tid] * inv;
    __syncthreads();
    if (tid < NCLS) {
        float acc = lb[tid];
#pragma unroll 4
        for (int d = 0; d < 128; d++) acc += s[d] * lw[tid * 128 + d];
        out[g * NCLS + tid] = acc;
    }
}

extern "C" void kernel_launch(void* const* d_in, const int* in_sizes, int n_in,
                              void* d_out, int out_size) {
    int o = (n_in >= 12) ? 1 : 0;
    const int* x     = (const int*)d_in[0];
    const int* ei    = (const int*)d_in[1];
    const int* et    = (const int*)d_in[2];
    const int* batch = (const int*)d_in[3];
    const int* nt    = (const int*)d_in[4];
    const float* emb    = (const float*)d_in[5 + o];
    const float* w_root = (const float*)d_in[6 + o];
    const float* w_rel  = (const float*)d_in[7 + o];
    const float* bias   = (const float*)d_in[8 + o];
    const float* lw     = (const float*)d_in[9 + o];
    const float* lb     = (const float*)d_in[10 + o];
    float* out = (float*)d_out;

    k_proj<<<dim3(9, 25), 128>>>(emb, w_rel, w_root);
    k_prep<<<(N_NODES + 255) / 256, 256>>>(x, nt, batch);
    k_build<<<(N_EDGES / 4 + 255) / 256, 256>>>(ei, et);
    k_gather<<<(N_NODES * 32 + 255) / 256, 256>>>(bias);
    k_out<<<NG, 128>>>(lw, lb, out);
    (void)in_sizes; (void)out_size;
}

// round 8
// speedup vs baseline: 1.1090x; 1.1085x over previous
#include <cuda_runtime.h>
#include <cuda_bf16.h>

#define N_NODES 100000
#define N_EDGES 1600000
#define NRELS 8
#define HID 128
#define N_TYPES 250
#define NG 64
#define NCLS 49
#define MAXDEG 64

// ---- scratch (device globals; no allocation allowed) ----
__device__ __align__(16) float g_projr[N_TYPES * HID];                 // fp32 root proj (+bias), 128 KB
__device__ __align__(16) __nv_bfloat16 g_projh[N_TYPES * NRELS * HID]; // bf16 rel proj, 512 KB
__device__ int g_cur[N_NODES];                                         // bucket fill
__device__ unsigned short g_csr[(size_t)N_NODES * MAXDEG];             // 12.8 MB keys (t*8+r)
__device__ unsigned char g_type8[N_NODES];                             // 100 KB
__device__ unsigned char g_msk[N_NODES];                               // 100 KB
__device__ int g_list[N_NODES];                                        // packed n|g<<17|t<<23
__device__ int g_ncount = 0;
__device__ float g_seg[NG * HID];
__device__ float g_segcnt[NG];

// proj = emb @ [w_rel_0..7 | w_root]; rel part bf16, root part fp32 with bias
// pre-folded. Also resets g_ncount (stream-ordered before k_prep).
__global__ void k_proj(const float* __restrict__ emb,
                       const float* __restrict__ w_rel,
                       const float* __restrict__ w_root,
                       const float* __restrict__ bias) {
    __shared__ float semb[10][128];
    int bx = blockIdx.x;           // 0..7 = rel r, 8 = root
    int y0 = blockIdx.y * 10;
    int tid = threadIdx.x;
    if (bx == 8 && blockIdx.y == 0 && tid == 0) g_ncount = 0;
    for (int idx = tid; idx < 10 * 128; idx += 128) {
        int row = idx >> 7, d = idx & 127;
        semb[row][d] = emb[(y0 + row) * 128 + d];
    }
    __syncthreads();
    float acc[10];
#pragma unroll
    for (int t = 0; t < 10; t++) acc[t] = 0.f;
    const float* wp = (bx < 8) ? (w_rel + (size_t)bx * 128 * 128 + tid)
                               : (w_root + tid);
#pragma unroll 4
    for (int d = 0; d < 128; d++) {
        float wv = wp[(size_t)d * 128];
#pragma unroll
        for (int t = 0; t < 10; t++) acc[t] += semb[t][d] * wv;
    }
    if (bx < 8) {
#pragma unroll
        for (int t = 0; t < 10; t++)
            g_projh[((y0 + t) * NRELS + bx) * HID + tid] = __float2bfloat16_rn(acc[t]);
    } else {
        float bv = bias[tid];
#pragma unroll
        for (int t = 0; t < 10; t++)
            g_projr[(y0 + t) * HID + tid] = acc[t] + bv;
    }
}

// One coalesced pass over nodes: byte tables, counter reset, warp-aggregated
// compaction, match-aggregated per-graph counts, seg zeroing.
__global__ void k_prep(const int* __restrict__ x,
                       const int* __restrict__ nt,
                       const int* __restrict__ batch) {
    int n = blockIdx.x * blockDim.x + threadIdx.x;
    int lane = threadIdx.x & 31;
    if (n < NG * HID) g_seg[n] = 0.f;
    if (n < NG) g_segcnt[n] = 0.f;
    bool valid = (n < N_NODES);
    int t = 0, m = 1, g = 0;
    if (valid) {
        t = x[n]; m = nt[n]; g = batch[n];
        g_type8[n] = (unsigned char)t;
        g_msk[n] = (m == 0) ? 1 : 0;
        g_cur[n] = 0;
    }
    bool keep = valid && (m == 0);
    unsigned full = 0xffffffffu;
    unsigned ball = __ballot_sync(full, keep);
    int cnt = __popc(ball);
    int base = 0;
    if (lane == 0 && cnt) base = atomicAdd(&g_ncount, cnt);
    base = __shfl_sync(full, base, 0);
    if (keep) {
        int pos = base + __popc(ball & ((1u << lane) - 1u));
        g_list[pos] = n | (g << 17) | (t << 23);
    }
    unsigned grp = __match_any_sync(full, keep ? g : -1);
    if (keep && lane == (__ffs(grp) - 1))
        atomicAdd(&g_segcnt[g], (float)__popc(grp));
}

// Bucket-CSR build: 8 edges/thread, byte tables (R5 measured-best shape).
__global__ void k_build(const int* __restrict__ ei,
                        const int* __restrict__ et) {
    int e8 = blockIdx.x * blockDim.x + threadIdx.x;
    if (e8 >= N_EDGES / 8) return;
    const int4* s4 = (const int4*)ei;
    const int4* d4 = (const int4*)(ei + N_EDGES);
    const int4* r4 = (const int4*)et;
    int4 sa = s4[e8 * 2], sb = s4[e8 * 2 + 1];
    int4 da = d4[e8 * 2], db = d4[e8 * 2 + 1];
    int4 ra = r4[e8 * 2], rb = r4[e8 * 2 + 1];
    int ss[8] = {sa.x, sa.y, sa.z, sa.w, sb.x, sb.y, sb.z, sb.w};
    int dd[8] = {da.x, da.y, da.z, da.w, db.x, db.y, db.z, db.w};
    int rr[8] = {ra.x, ra.y, ra.z, ra.w, rb.x, rb.y, rb.z, rb.w};
    unsigned char mk[8];
#pragma unroll
    for (int j = 0; j < 8; j++) mk[j] = g_msk[dd[j]];
#pragma unroll
    for (int j = 0; j < 8; j++) {
        if (!mk[j]) continue;
        int t = g_type8[ss[j]];
        int slot = atomicAdd(&g_cur[dd[j]], 1);
        if (slot < MAXDEG)
            g_csr[(size_t)dd[j] * MAXDEG + slot] = (unsigned short)(t * NRELS + rr[j]);
    }
}

// One warp per unmasked node. Rel counts via ballots; smem stage holds
// ({w,w} packed f32x2, byte-offset into bf16 table) per message (pads w=0);
// inner loop: LDS.128 + LDG.64(bf16 uint2) + 4 ALU decode + 2 fma.rn.f32x2.
__global__ void k_gather() {
    __shared__ ulonglong2 sbuf[8][MAXDEG];
    int gt = blockIdx.x * blockDim.x + threadIdx.x;
    int idx = gt >> 5;
    int lane = gt & 31;
    int wslot = threadIdx.x >> 5;
    if (idx >= g_ncount) return;
    int packed = g_list[idx];
    int n = packed & 0x1ffff;
    int g = (packed >> 17) & 63;
    int t0 = packed >> 23;

    // root + bias (bias pre-folded in table)
    float4 rt = ((const float4*)g_projr)[t0 * 32 + lane];
    unsigned long long acc01, acc23;
    asm("mov.b64 %0, {%1,%2};" : "=l"(acc01) : "f"(rt.x), "f"(rt.y));
    asm("mov.b64 %0, {%1,%2};" : "=l"(acc23) : "f"(rt.z), "f"(rt.w));

    int deg = min(g_cur[n], MAXDEG);
    const unsigned short* row = g_csr + (size_t)n * MAXDEG;
    int ka = row[lane];
    int kb = row[lane + 32];
    int ra = ka & 7, rb = kb & 7;

    unsigned mA = (deg >= 32) ? 0xffffffffu : ((1u << deg) - 1u);
    int d2 = deg - 32;
    unsigned mB = (d2 <= 0) ? 0u : ((d2 >= 32) ? 0xffffffffu : ((1u << d2) - 1u));
    unsigned full = 0xffffffffu;
    unsigned a0 = __ballot_sync(full, ra & 1), a1 = __ballot_sync(full, ra & 2), a2 = __ballot_sync(full, ra & 4);
    unsigned b0 = __ballot_sync(full, rb & 1), b1 = __ballot_sync(full, rb & 2), b2 = __ballot_sync(full, rb & 4);
    unsigned sa = ((ra & 1) ? a0 : ~a0) & ((ra & 2) ? a1 : ~a1) & ((ra & 4) ? a2 : ~a2);
    unsigned sb = ((ra & 1) ? b0 : ~b0) & ((ra & 2) ? b1 : ~b1) & ((ra & 4) ? b2 : ~b2);
    int ca = __popc(sa & mA) + __popc(sb & mB);
    float wa = 1.0f / fmaxf((float)ca, 1.0f);
    unsigned ua = ((rb & 1) ? a0 : ~a0) & ((rb & 2) ? a1 : ~a1) & ((rb & 4) ? a2 : ~a2);
    unsigned ub = ((rb & 1) ? b0 : ~b0) & ((rb & 2) ? b1 : ~b1) & ((rb & 4) ? b2 : ~b2);
    int cb = __popc(ua & mA) + __popc(ub & mB);
    float wb = 1.0f / fmaxf((float)cb, 1.0f);

    // Stage resolved messages: pads get w=0 (stale CSR keys are always in-range).
    unsigned wau = __float_as_uint((lane < deg) ? wa : 0.f);
    unsigned wbu = __float_as_uint((lane + 32 < deg) ? wb : 0.f);
    sbuf[wslot][lane] = make_ulonglong2(((unsigned long long)wau << 32) | wau,
                                        (unsigned long long)(unsigned)(ka * 256));
    sbuf[wslot][lane + 32] = make_ulonglong2(((unsigned long long)wbu << 32) | wbu,
                                             (unsigned long long)(unsigned)(kb * 256));
    __syncwarp();

    const char* basep = (const char*)g_projh + lane * 8;
    int degR = (deg + 7) & ~7;
    for (int i = 0; i < degR; i += 8) {
#pragma unroll
        for (int j = 0; j < 8; j++) {
            ulonglong2 s = sbuf[wslot][i + j];
            const char* p = basep + s.y;
            unsigned vx, vy;
            asm("ld.global.nc.v2.u32 {%0,%1}, [%2];" : "=r"(vx), "=r"(vy) : "l"(p));
            unsigned e0 = vx << 16, e1 = vx & 0xffff0000u;
            unsigned e2 = vy << 16, e3 = vy & 0xffff0000u;
            unsigned long long v01, v23;
            asm("mov.b64 %0, {%1,%2};" : "=l"(v01) : "r"(e0), "r"(e1));
            asm("mov.b64 %0, {%1,%2};" : "=l"(v23) : "r"(e2), "r"(e3));
            asm("fma.rn.f32x2 %0, %1, %2, %0;" : "+l"(acc01) : "l"(v01), "l"(s.x));
            asm("fma.rn.f32x2 %0, %1, %2, %0;" : "+l"(acc23) : "l"(v23), "l"(s.x));
        }
    }

    float r0, r1, r2, r3;
    asm("mov.b64 {%0,%1}, %2;" : "=f"(r0), "=f"(r1) : "l"(acc01));
    asm("mov.b64 {%0,%1}, %2;" : "=f"(r2), "=f"(r3) : "l"(acc23));
    r0 = fmaxf(r0, 0.f); r1 = fmaxf(r1, 0.f);
    r2 = fmaxf(r2, 0.f); r3 = fmaxf(r3, 0.f);

    float* dstp = &g_seg[g * HID + lane * 4];
    asm volatile("red.global.add.v4.f32 [%0], {%1,%2,%3,%4};"
                 :: "l"(dstp), "f"(r0), "f"(r1), "f"(r2), "f"(r3)
                 : "memory");
}

// out[g][o] = (seg[g]/max(cnt,1)) . lin_w[o] + lin_b[o]
__global__ void k_out(const float* __restrict__ lw,
                      const float* __restrict__ lb,
                      float* __restrict__ out) {
    __shared__ float s[128];
    int g = blockIdx.x, tid = threadIdx.x;
    float c = g_segcnt[g];
    float inv = 1.0f / fmaxf(c, 1.0f);
    s[tid] = g_seg[g * HID + tid] * inv;
    __syncthreads();
    if (tid < NCLS) {
        float acc = lb[tid];
#pragma unroll 4
        for (int d = 0; d < 128; d++) acc += s[d] * lw[tid * 128 + d];
        out[g * NCLS + tid] = acc;
    }
}

extern "C" void kernel_launch(void* const* d_in, const int* in_sizes, int n_in,
                              void* d_out, int out_size) {
    int o = (n_in >= 12) ? 1 : 0;
    const int* x     = (const int*)d_in[0];
    const int* ei    = (const int*)d_in[1];
    const int* et    = (const int*)d_in[2];
    const int* batch = (const int*)d_in[3];
    const int* nt    = (const int*)d_in[4];
    const float* emb    = (const float*)d_in[5 + o];
    const float* w_root = (const float*)d_in[6 + o];
    const float* w_rel  = (const float*)d_in[7 + o];
    const float* bias   = (const float*)d_in[8 + o];
    const float* lw     = (const float*)d_in[9 + o];
    const float* lb     = (const float*)d_in[10 + o];
    float* out = (float*)d_out;

    k_proj<<<dim3(9, 25), 128>>>(emb, w_rel, w_root, bias);
    k_prep<<<(N_NODES + 255) / 256, 256>>>(x, nt, batch);
    k_build<<<(N_EDGES / 8 + 255) / 256, 256>>>(ei, et);
    k_gather<<<(N_NODES * 32 + 255) / 256, 256>>>();
    k_out<<<NG, 128>>>(lw, lb, out);
    (void)in_sizes; (void)out_size;
}

// round 9
// speedup vs baseline: 1.2035x; 1.0852x over previous
#include <cuda_runtime.h>
#include <cuda_bf16.h>

#define N_NODES 100000
#define N_EDGES 1600000
#define NRELS 8
#define HID 128
#define N_TYPES 250
#define NG 64
#define NCLS 49
#define MAXDEG 64
#define PROJ_BLOCKS 225   // 9 col-tiles x 25 row-chunks

// ---- scratch (device globals; no allocation allowed) ----
__device__ __align__(16) float g_projr[N_TYPES * HID];                 // fp32 root proj (+bias), 128 KB
__device__ __align__(16) __nv_bfloat16 g_projh[N_TYPES * NRELS * HID]; // bf16 rel proj, 512 KB
__device__ int g_cur[N_NODES];                                         // bucket fill
__device__ unsigned short g_csr[(size_t)N_NODES * MAXDEG];             // 12.8 MB keys (t*8+r)
__device__ unsigned char g_type8[N_NODES];                             // 100 KB
__device__ unsigned char g_msk[N_NODES];                               // 100 KB
__device__ int g_list[N_NODES];                                        // packed n|g<<17|t<<23
__device__ int g_ncount = 0;          // always 0 at kernel_launch entry; k_out re-zeroes it
__device__ float g_seg[NG * HID];
__device__ float g_segcnt[NG];

// Fused setup: blocks [0,225) compute proj tables; blocks [225, ...) do the
// node pass (byte tables, counter reset, warp-aggregated compaction,
// per-graph counts, seg zeroing). The two halves are independent.
__global__ void k_setup(const float* __restrict__ emb,
                        const float* __restrict__ w_rel,
                        const float* __restrict__ w_root,
                        const float* __restrict__ bias,
                        const int* __restrict__ x,
                        const int* __restrict__ nt,
                        const int* __restrict__ batch) {
    __shared__ float semb[10][128];
    int tid = threadIdx.x;
    if (blockIdx.x < PROJ_BLOCKS) {
        int bx = blockIdx.x % 9;            // 0..7 = rel r, 8 = root
        int y0 = (blockIdx.x / 9) * 10;
        for (int idx = tid; idx < 10 * 128; idx += 128) {
            int row = idx >> 7, d = idx & 127;
            semb[row][d] = emb[(y0 + row) * 128 + d];
        }
        __syncthreads();
        float acc[10];
#pragma unroll
        for (int t = 0; t < 10; t++) acc[t] = 0.f;
        const float* wp = (bx < 8) ? (w_rel + (size_t)bx * 128 * 128 + tid)
                                   : (w_root + tid);
#pragma unroll 4
        for (int d = 0; d < 128; d++) {
            float wv = wp[(size_t)d * 128];
#pragma unroll
            for (int t = 0; t < 10; t++) acc[t] += semb[t][d] * wv;
        }
        if (bx < 8) {
#pragma unroll
            for (int t = 0; t < 10; t++)
                g_projh[((y0 + t) * NRELS + bx) * HID + tid] = __float2bfloat16_rn(acc[t]);
        } else {
            float bv = bias[tid];
#pragma unroll
            for (int t = 0; t < 10; t++)
                g_projr[(y0 + t) * HID + tid] = acc[t] + bv;
        }
        return;
    }
    // ---- prep half ----
    int n = (blockIdx.x - PROJ_BLOCKS) * 128 + tid;
    int lane = tid & 31;
    if (n < NG * HID) g_seg[n] = 0.f;
    if (n < NG) g_segcnt[n] = 0.f;
    bool valid = (n < N_NODES);
    int t = 0, m = 1, g = 0;
    if (valid) {
        t = x[n]; m = nt[n]; g = batch[n];
        g_type8[n] = (unsigned char)t;
        g_msk[n] = (m == 0) ? 1 : 0;
        g_cur[n] = 0;
    }
    bool keep = valid && (m == 0);
    unsigned full = 0xffffffffu;
    unsigned ball = __ballot_sync(full, keep);
    int cnt = __popc(ball);
    int base = 0;
    if (lane == 0 && cnt) base = atomicAdd(&g_ncount, cnt);
    base = __shfl_sync(full, base, 0);
    if (keep) {
        int pos = base + __popc(ball & ((1u << lane) - 1u));
        g_list[pos] = n | (g << 17) | (t << 23);
    }
    unsigned grp = __match_any_sync(full, keep ? g : -1);
    if (keep && lane == (__ffs(grp) - 1))
        atomicAdd(&g_segcnt[g], (float)__popc(grp));
}

// Bucket-CSR build: 8 edges/thread, byte tables (measured-best shape).
__global__ void k_build(const int* __restrict__ ei,
                        const int* __restrict__ et) {
    int e8 = blockIdx.x * blockDim.x + threadIdx.x;
    if (e8 >= N_EDGES / 8) return;
    const int4* s4 = (const int4*)ei;
    const int4* d4 = (const int4*)(ei + N_EDGES);
    const int4* r4 = (const int4*)et;
    int4 sa = s4[e8 * 2], sb = s4[e8 * 2 + 1];
    int4 da = d4[e8 * 2], db = d4[e8 * 2 + 1];
    int4 ra = r4[e8 * 2], rb = r4[e8 * 2 + 1];
    int ss[8] = {sa.x, sa.y, sa.z, sa.w, sb.x, sb.y, sb.z, sb.w};
    int dd[8] = {da.x, da.y, da.z, da.w, db.x, db.y, db.z, db.w};
    int rr[8] = {ra.x, ra.y, ra.z, ra.w, rb.x, rb.y, rb.z, rb.w};
    unsigned char mk[8];
#pragma unroll
    for (int j = 0; j < 8; j++) mk[j] = g_msk[dd[j]];
#pragma unroll
    for (int j = 0; j < 8; j++) {
        if (!mk[j]) continue;
        int t = g_type8[ss[j]];
        int slot = atomicAdd(&g_cur[dd[j]], 1);
        if (slot < MAXDEG)
            g_csr[(size_t)dd[j] * MAXDEG + slot] = (unsigned short)(t * NRELS + rr[j]);
    }
}

// One warp per unmasked node. Rel counts via ballots (B-side skipped when
// deg<=32); smem stage holds {w,w,offIdx}; inner loop per message:
// LDS.128 + IMAD.WIDE + LDG.64(bf16 uint2) + 4 ALU decode + 2 fma.rn.f32x2.
__global__ void __launch_bounds__(256, 8) k_gather() {
    __shared__ uint4 sbuf[8][MAXDEG];
    int gt = blockIdx.x * blockDim.x + threadIdx.x;
    int idx = gt >> 5;
    int lane = gt & 31;
    int wslot = threadIdx.x >> 5;
    if (idx >= g_ncount) return;
    int packed = g_list[idx];
    int n = packed & 0x1ffff;
    int g = (packed >> 17) & 63;
    int t0 = packed >> 23;

    // root + bias (bias pre-folded in table)
    float4 rt = ((const float4*)g_projr)[t0 * 32 + lane];
    unsigned long long acc01, acc23;
    asm("mov.b64 %0, {%1,%2};" : "=l"(acc01) : "f"(rt.x), "f"(rt.y));
    asm("mov.b64 %0, {%1,%2};" : "=l"(acc23) : "f"(rt.z), "f"(rt.w));

    int deg = min(g_cur[n], MAXDEG);
    const unsigned short* row = g_csr + (size_t)n * MAXDEG;
    int ka = row[lane];
    int ra = ka & 7;
    unsigned full = 0xffffffffu;

    unsigned a0 = __ballot_sync(full, ra & 1), a1 = __ballot_sync(full, ra & 2), a2 = __ballot_sync(full, ra & 4);

    if (deg <= 32) {   // warp-uniform; ~99.99% of nodes (deg ~ Poisson(16))
        unsigned mA = (deg >= 32) ? full : ((1u << deg) - 1u);
        unsigned sa = ((ra & 1) ? a0 : ~a0) & ((ra & 2) ? a1 : ~a1) & ((ra & 4) ? a2 : ~a2);
        int ca = __popc(sa & mA);
        float wa = 1.0f / fmaxf((float)ca, 1.0f);
        unsigned wau = __float_as_uint((lane < deg) ? wa : 0.f);
        sbuf[wslot][lane] = make_uint4(wau, wau, (unsigned)(ka * 32), 0u);
    } else {
        int kb = row[lane + 32];
        int rb = kb & 7;
        unsigned mA = full;
        int d2 = deg - 32;
        unsigned mB = (d2 >= 32) ? full : ((1u << d2) - 1u);
        unsigned b0 = __ballot_sync(full, rb & 1), b1 = __ballot_sync(full, rb & 2), b2 = __ballot_sync(full, rb & 4);
        unsigned sa = ((ra & 1) ? a0 : ~a0) & ((ra & 2) ? a1 : ~a1) & ((ra & 4) ? a2 : ~a2);
        unsigned sb = ((ra & 1) ? b0 : ~b0) & ((ra & 2) ? b1 : ~b1) & ((ra & 4) ? b2 : ~b2);
        int ca = __popc(sa & mA) + __popc(sb & mB);
        float wa = 1.0f / fmaxf((float)ca, 1.0f);
        unsigned ua = ((rb & 1) ? a0 : ~a0) & ((rb & 2) ? a1 : ~a1) & ((rb & 4) ? a2 : ~a2);
        unsigned ub = ((rb & 1) ? b0 : ~b0) & ((rb & 2) ? b1 : ~b1) & ((rb & 4) ? b2 : ~b2);
        int cb = __popc(ua & mA) + __popc(ub & mB);
        float wb = 1.0f / fmaxf((float)cb, 1.0f);
        unsigned wau = __float_as_uint(wa);
        unsigned wbu = __float_as_uint((lane + 32 < deg) ? wb : 0.f);
        sbuf[wslot][lane]      = make_uint4(wau, wau, (unsigned)(ka * 32), 0u);
        sbuf[wslot][lane + 32] = make_uint4(wbu, wbu, (unsigned)(kb * 32), 0u);
    }
    __syncwarp();

    const uint2* ph2 = (const uint2*)g_projh + lane;   // lane-fixed 64-bit base
    int degR = (deg + 7) & ~7;
    for (int i = 0; i < degR; i += 8) {
#pragma unroll
        for (int j = 0; j < 8; j++) {
            uint4 s = sbuf[wslot][i + j];
            unsigned long long ww;
            asm("mov.b64 %0, {%1,%2};" : "=l"(ww) : "r"(s.x), "r"(s.y));
            uint2 v = ph2[s.z];                         // IMAD.WIDE + LDG.64
            unsigned e0 = v.x << 16, e1 = v.x & 0xffff0000u;
            unsigned e2 = v.y << 16, e3 = v.y & 0xffff0000u;
            unsigned long long v01, v23;
            asm("mov.b64 %0, {%1,%2};" : "=l"(v01) : "r"(e0), "r"(e1));
            asm("mov.b64 %0, {%1,%2};" : "=l"(v23) : "r"(e2), "r"(e3));
            asm("fma.rn.f32x2 %0, %1, %2, %0;" : "+l"(acc01) : "l"(v01), "l"(ww));
            asm("fma.rn.f32x2 %0, %1, %2, %0;" : "+l"(acc23) : "l"(v23), "l"(ww));
        }
    }

    float r0, r1, r2, r3;
    asm("mov.b64 {%0,%1}, %2;" : "=f"(r0), "=f"(r1) : "l"(acc01));
    asm("mov.b64 {%0,%1}, %2;" : "=f"(r2), "=f"(r3) : "l"(acc23));
    r0 = fmaxf(r0, 0.f); r1 = fmaxf(r1, 0.f);
    r2 = fmaxf(r2, 0.f); r3 = fmaxf(r3, 0.f);

    float* dstp = &g_seg[g * HID + lane * 4];
    asm volatile("red.global.add.v4.f32 [%0], {%1,%2,%3,%4};"
                 :: "l"(dstp), "f"(r0), "f"(r1), "f"(r2), "f"(r3)
                 : "memory");
}

// out[g][o] = (seg[g]/max(cnt,1)) . lin_w[o] + lin_b[o]; re-zero g_ncount
// so the next kernel_launch call starts from 0 (invariant, not a guard).
__global__ void k_out(const float* __restrict__ lw,
                      const float* __restrict__ lb,
                      float* __restrict__ out) {
    __shared__ float s[128];
    int g = blockIdx.x, tid = threadIdx.x;
    float c = g_segcnt[g];
    float inv = 1.0f / fmaxf(c, 1.0f);
    s[tid] = g_seg[g * HID + tid] * inv;
    __syncthreads();
    if (tid < NCLS) {
        float acc = lb[tid];
#pragma unroll 4
        for (int d = 0; d < 128; d++) acc += s[d] * lw[tid * 128 + d];
        out[g * NCLS + tid] = acc;
    }
    if (g == 0 && tid == 0) g_ncount = 0;
}

extern "C" void kernel_launch(void* const* d_in, const int* in_sizes, int n_in,
                              void* d_out, int out_size) {
    int o = (n_in >= 12) ? 1 : 0;
    const int* x     = (const int*)d_in[0];
    const int* ei    = (const int*)d_in[1];
    const int* et    = (const int*)d_in[2];
    const int* batch = (const int*)d_in[3];
    const int* nt    = (const int*)d_in[4];
    const float* emb    = (const float*)d_in[5 + o];
    const float* w_root = (const float*)d_in[6 + o];
    const float* w_rel  = (const float*)d_in[7 + o];
    const float* bias   = (const float*)d_in[8 + o];
    const float* lw     = (const float*)d_in[9 + o];
    const float* lb     = (const float*)d_in[10 + o];
    float* out = (float*)d_out;

    int prep_blocks = (N_NODES + 127) / 128;
    k_setup<<<PROJ_BLOCKS + prep_blocks, 128>>>(emb, w_rel, w_root, bias, x, nt, batch);
    k_build<<<(N_EDGES / 8 + 255) / 256, 256>>>(ei, et);
    k_gather<<<(N_NODES * 32 + 255) / 256, 256>>>();
    k_out<<<NG, 128>>>(lw, lb, out);
    (void)in_sizes; (void)out_size;
}

// round 12
// speedup vs baseline: 1.2791x; 1.0628x over previous
#include <cuda_runtime.h>
#include <cuda_bf16.h>

#define N_NODES 100000
#define N_EDGES 1600000
#define NRELS 8
#define HID 128
#define N_TYPES 250
#define NG 64
#define NCLS 49
#define MAXDEG 64
#define PROJ_BLOCKS 225   // 9 col-tiles x 25 row-chunks

// ---- scratch (device globals; no allocation allowed) ----
__device__ __align__(16) float g_projr[N_TYPES * HID];                 // fp32 root proj (+bias), 128 KB
__device__ __align__(16) __nv_bfloat16 g_projh[N_TYPES * NRELS * HID]; // bf16 rel proj, 512 KB
__device__ int g_cur[N_NODES];                                         // bucket fill
__device__ unsigned short g_csr[(size_t)N_NODES * MAXDEG];             // 12.8 MB keys (t*8+r)
__device__ unsigned char g_type8[N_NODES];                             // 100 KB
__device__ unsigned char g_msk[N_NODES];                               // 100 KB
__device__ int g_list[N_NODES];                                        // packed n|g<<17|t<<23
__device__ int g_ncount = 0;          // always 0 at kernel_launch entry; k_out re-zeroes it
__device__ float g_seg[NG * HID];
__device__ float g_segcnt[NG];

// Fused setup: blocks [0,225) compute proj tables; the rest do the node pass
// (byte tables, counter reset, warp-aggregated compaction, per-graph counts,
// seg zeroing). The two halves are independent.
__global__ void k_setup(const float* __restrict__ emb,
                        const float* __restrict__ w_rel,
                        const float* __restrict__ w_root,
                        const float* __restrict__ bias,
                        const int* __restrict__ x,
                        const int* __restrict__ nt,
                        const int* __restrict__ batch) {
    __shared__ float semb[10][128];
    const int tid = threadIdx.x;
    if (blockIdx.x < PROJ_BLOCKS) {
        const int bx = blockIdx.x % 9;      // 0..7 = rel r, 8 = root
        const int y0 = (blockIdx.x / 9) * 10;
        for (int idx = tid; idx < 1280; idx += 128) {
            semb[idx >> 7][idx & 127] = emb[(y0 + (idx >> 7)) * 128 + (idx & 127)];
        }
        __syncthreads();
        float acc[10];
#pragma unroll
        for (int t = 0; t < 10; t++) acc[t] = 0.f;
        const float* wp = (bx < 8) ? (w_rel + (size_t)bx * 16384 + tid)
                                   : (w_root + tid);
#pragma unroll 4
        for (int d = 0; d < 128; d++) {
            float wv = wp[(size_t)d * 128];
#pragma unroll
            for (int t = 0; t < 10; t++) acc[t] += semb[t][d] * wv;
        }
        if (bx < 8) {
#pragma unroll
            for (int t = 0; t < 10; t++)
                g_projh[((y0 + t) * NRELS + bx) * HID + tid] = __float2bfloat16_rn(acc[t]);
        } else {
            const float bv = bias[tid];
#pragma unroll
            for (int t = 0; t < 10; t++)
                g_projr[(y0 + t) * HID + tid] = acc[t] + bv;
        }
        return;
    }
    // ---- prep half ----
    const int n = (blockIdx.x - PROJ_BLOCKS) * 128 + tid;
    const int lane = tid & 31;
    if (n < NG * HID) g_seg[n] = 0.f;
    if (n < NG) g_segcnt[n] = 0.f;
    const bool valid = (n < N_NODES);
    int t = 0, m = 1, g = 0;
    if (valid) {
        t = x[n]; m = nt[n]; g = batch[n];
        g_type8[n] = (unsigned char)t;
        g_msk[n] = (m == 0) ? 1 : 0;
        g_cur[n] = 0;
    }
    const bool keep = valid && (m == 0);
    const unsigned full = 0xffffffffu;
    const unsigned ball = __ballot_sync(full, keep);
    const int cnt = __popc(ball);
    int base = 0;
    if (lane == 0 && cnt) base = atomicAdd(&g_ncount, cnt);
    base = __shfl_sync(full, base, 0);
    if (keep) {
        int pos = base + __popc(ball & ((1u << lane) - 1u));
        g_list[pos] = n | (g << 17) | (t << 23);
    }
    const unsigned grp = __match_any_sync(full, keep ? g : -1);
    if (keep && lane == (__ffs(grp) - 1))
        atomicAdd(&g_segcnt[g], (float)__popc(grp));
}

// Bucket-CSR build: 4 edges/thread -> 400K threads (full occupancy),
// byte tables, conditional atomics.
__global__ void __launch_bounds__(256, 8) k_build(const int* __restrict__ ei,
                                                  const int* __restrict__ et) {
    const int e4 = blockIdx.x * blockDim.x + threadIdx.x;
    if (e4 >= N_EDGES / 4) return;
    const int4 sv = ((const int4*)ei)[e4];
    const int4 dv = ((const int4*)(ei + N_EDGES))[e4];
    const int4 rv = ((const int4*)et)[e4];
    const int ss[4] = {sv.x, sv.y, sv.z, sv.w};
    const int dd[4] = {dv.x, dv.y, dv.z, dv.w};
    const int rr[4] = {rv.x, rv.y, rv.z, rv.w};
    unsigned char mk[4];
#pragma unroll
    for (int j = 0; j < 4; j++) mk[j] = g_msk[dd[j]];
#pragma unroll
    for (int j = 0; j < 4; j++) {
        if (!mk[j]) continue;
        const int ty = g_type8[ss[j]];
        const int slot = atomicAdd(&g_cur[dd[j]], 1);
        if (slot < MAXDEG)
            g_csr[(size_t)dd[j] * MAXDEG + slot] = (unsigned short)(ty * NRELS + rr[j]);
    }
}

// One warp per unmasked node. Rel counts via ballots (B-side skipped when
// deg<=32); smem stage holds {w,w,offIdx}; inner loop per message:
// LDS.128 + IMAD.WIDE + LDG.64(bf16 uint2) + 4 ALU decode + 2 fma.rn.f32x2.
__global__ void __launch_bounds__(256, 8) k_gather() {
    __shared__ uint4 sbuf[8][MAXDEG];
    const int gt = blockIdx.x * blockDim.x + threadIdx.x;
    const int idx = gt >> 5;
    const int lane = gt & 31;
    const int wslot = threadIdx.x >> 5;
    if (idx >= g_ncount) return;
    const int packed = g_list[idx];
    const int n = packed & 0x1ffff;
    const int g = (packed >> 17) & 63;
    const int t0 = packed >> 23;

    // root + bias (bias pre-folded in table)
    const float4 rt = ((const float4*)g_projr)[t0 * 32 + lane];
    unsigned long long acc01, acc23;
    asm("mov.b64 %0, {%1,%2};" : "=l"(acc01) : "f"(rt.x), "f"(rt.y));
    asm("mov.b64 %0, {%1,%2};" : "=l"(acc23) : "f"(rt.z), "f"(rt.w));

    const int deg = min(g_cur[n], MAXDEG);
    const unsigned short* row = g_csr + (size_t)n * MAXDEG;
    const int ka = row[lane];
    const int ra = ka & 7;
    const unsigned full = 0xffffffffu;

    const unsigned a0 = __ballot_sync(full, ra & 1);
    const unsigned a1 = __ballot_sync(full, ra & 2);
    const unsigned a2 = __ballot_sync(full, ra & 4);

    if (deg <= 32) {   // warp-uniform; ~99.99% of nodes (deg ~ Poisson(16))
        const unsigned mA = (deg >= 32) ? full : ((1u << deg) - 1u);
        const unsigned sa = ((ra & 1) ? a0 : ~a0) & ((ra & 2) ? a1 : ~a1) & ((ra & 4) ? a2 : ~a2);
        const float wa = 1.0f / fmaxf((float)__popc(sa & mA), 1.0f);
        const unsigned wau = __float_as_uint((lane < deg) ? wa : 0.f);
        sbuf[wslot][lane] = make_uint4(wau, wau, (unsigned)(ka * 32), 0u);
    } else {
        const int kb = row[lane + 32];
        const int rb = kb & 7;
        const int d2 = deg - 32;
        const unsigned mB = (d2 >= 32) ? full : ((1u << d2) - 1u);
        const unsigned b0 = __ballot_sync(full, rb & 1);
        const unsigned b1 = __ballot_sync(full, rb & 2);
        const unsigned b2 = __ballot_sync(full, rb & 4);
        const unsigned sa = ((ra & 1) ? a0 : ~a0) & ((ra & 2) ? a1 : ~a1) & ((ra & 4) ? a2 : ~a2);
        const unsigned sb = ((ra & 1) ? b0 : ~b0) & ((ra & 2) ? b1 : ~b1) & ((ra & 4) ? b2 : ~b2);
        const float wa = 1.0f / fmaxf((float)(__popc(sa) + __popc(sb & mB)), 1.0f);
        const unsigned ua = ((rb & 1) ? a0 : ~a0) & ((rb & 2) ? a1 : ~a1) & ((rb & 4) ? a2 : ~a2);
        const unsigned ub = ((rb & 1) ? b0 : ~b0) & ((rb & 2) ? b1 : ~b1) & ((rb & 4) ? b2 : ~b2);
        const float wb = 1.0f / fmaxf((float)(__popc(ua) + __popc(ub & mB)), 1.0f);
        const unsigned wau = __float_as_uint(wa);
        const unsigned wbu = __float_as_uint((lane + 32 < deg) ? wb : 0.f);
        sbuf[wslot][lane]      = make_uint4(wau, wau, (unsigned)(ka * 32), 0u);
        sbuf[wslot][lane + 32] = make_uint4(wbu, wbu, (unsigned)(kb * 32), 0u);
    }
    __syncwarp();

    const uint2* ph2 = (const uint2*)g_projh + lane;   // lane-fixed 64-bit base
    const int degR = (deg + 7) & ~7;
    for (int i = 0; i < degR; i += 8) {
#pragma unroll
        for (int j = 0; j < 8; j++) {
            const uint4 s = sbuf[wslot][i + j];
            unsigned long long ww;
            asm("mov.b64 %0, {%1,%2};" : "=l"(ww) : "r"(s.x), "r"(s.y));
            const uint2 v = ph2[s.z];                   // IMAD.WIDE + LDG.64
            const unsigned e0 = v.x << 16, e1 = v.x & 0xffff0000u;
            const unsigned e2 = v.y << 16, e3 = v.y & 0xffff0000u;
            unsigned long long v01, v23;
            asm("mov.b64 %0, {%1,%2};" : "=l"(v01) : "r"(e0), "r"(e1));
            asm("mov.b64 %0, {%1,%2};" : "=l"(v23) : "r"(e2), "r"(e3));
            asm("fma.rn.f32x2 %0, %1, %2, %0;" : "+l"(acc01) : "l"(v01), "l"(ww));
            asm("fma.rn.f32x2 %0, %1, %2, %0;" : "+l"(acc23) : "l"(v23), "l"(ww));
        }
    }

    float r0, r1, r2, r3;
    asm("mov.b64 {%0,%1}, %2;" : "=f"(r0), "=f"(r1) : "l"(acc01));
    asm("mov.b64 {%0,%1}, %2;" : "=f"(r2), "=f"(r3) : "l"(acc23));
    r0 = fmaxf(r0, 0.f); r1 = fmaxf(r1, 0.f);
    r2 = fmaxf(r2, 0.f); r3 = fmaxf(r3, 0.f);

    float* dstp = &g_seg[g * HID + lane * 4];
    asm volatile("red.global.add.v4.f32 [%0], {%1,%2,%3,%4};"
                 :: "l"(dstp), "f"(r0), "f"(r1), "f"(r2), "f"(r3)
                 : "memory");
}

// out[g][o] = (seg[g]/max(cnt,1)) . lin_w[o] + lin_b[o].
// lw staged in smem COALESCED, row stride 129 (conflict-free column walk).
// Re-zeroes g_ncount so the next kernel_launch call starts from 0.
__global__ void k_out(const float* __restrict__ lw,
                      const float* __restrict__ lb,
                      float* __restrict__ out) {
    __shared__ float sv[HID];
    __shared__ float slw[NCLS * 129];
    const int g = blockIdx.x;
    const int tid = threadIdx.x;
#pragma unroll
    for (int k = 0; k < (NCLS * HID + 127) / 128; k++) {
        int i = k * 128 + tid;
        if (i < NCLS * HID) slw[(i >> 7) * 129 + (i & 127)] = lw[i];
    }
    const float inv = 1.0f / fmaxf(g_segcnt[g], 1.0f);
    sv[tid] = g_seg[g * HID + tid] * inv;
    __syncthreads();
    if (tid < NCLS) {
        float acc = lb[tid];
        const float* wrow = &slw[tid * 129];
#pragma unroll 8
        for (int d = 0; d < HID; d++) acc += sv[d] * wrow[d];
        out[g * NCLS + tid] = acc;
    }
    if (g == 0 && tid == 0) g_ncount = 0;
}

extern "C" void kernel_launch(void* const* d_in, const int* in_sizes, int n_in,
                              void* d_out, int out_size) {
    const int o = (n_in >= 12) ? 1 : 0;
    const int* x     = (const int*)d_in[0];
    const int* ei    = (const int*)d_in[1];
    const int* et    = (const int*)d_in[2];
    const int* batch = (const int*)d_in[3];
    const int* nt    = (const int*)d_in[4];
    const float* emb    = (const float*)d_in[5 + o];
    const float* w_root = (const float*)d_in[6 + o];
    const float* w_rel  = (const float*)d_in[7 + o];
    const float* bias   = (const float*)d_in[8 + o];
    const float* lw     = (const float*)d_in[9 + o];
    const float* lb     = (const float*)d_in[10 + o];
    float* out = (float*)d_out;

    const int prep_blocks = (N_NODES + 127) / 128;
    k_setup<<<PROJ_BLOCKS + prep_blocks, 128>>>(emb, w_rel, w_root, bias, x, nt, batch);
    k_build<<<(N_EDGES / 4 + 255) / 256, 256>>>(ei, et);
    k_gather<<<(N_NODES * 32 + 255) / 256, 256>>>();
    k_out<<<NG, 128>>>(lw, lb, out);
    (void)in_sizes; (void)out_size;
}